// round 2
// baseline (speedup 1.0000x reference)
#include <cuda_runtime.h>
#include <cstdint>
#include <cstddef>

// ---------------------------------------------------------------------------
// AttentionLayer: B=4, N=4096, Kn=32, F=64, H=16, D=16 (fp32)
//
// Faithful-reshape semantics:
//   K[h,k,d] = KP[2h + (k>>4), (k&15)*16 + d],  KP = inp @ Wk + bk  [32 x 256]
//   V[h,k,d] = VP[2h + (k>>4), (k&15)*16 + d],  VP = inp @ Wv + bv
//   s[h,k]   = 0.25 * Q_h . K[h,k,:]  ; w = softmax_k(s)
//   out[h*16+d] = sum_k w[h,k] * V[h,k,d]
// Qh = query @ Wq + bq precomputed by a small kernel into global scratch.
// ---------------------------------------------------------------------------

#define FULLMASK 0xffffffffu

constexpr int PTS     = 16384;
constexpr int GRID    = 152;
constexpr int PPB     = 108;          // 152*108 = 16416 >= 16384
constexpr int THREADS = 512;

__device__ float g_Qh[(size_t)PTS * 256];

__device__ __forceinline__ void cp16(void* dst_smem, const void* src) {
    uint32_t d = (uint32_t)__cvta_generic_to_shared(dst_smem);
    asm volatile("cp.async.ca.shared.global [%0], [%1], 16;" :: "r"(d), "l"(src) : "memory");
}
__device__ __forceinline__ void cp_commit() { asm volatile("cp.async.commit_group;" ::: "memory"); }
template <int N> __device__ __forceinline__ void cp_wait() {
    asm volatile("cp.async.wait_group %0;" :: "n"(N) : "memory");
}
__device__ __forceinline__ float dot4(float4 a, float4 b, float acc) {
    return fmaf(a.x, b.x, fmaf(a.y, b.y, fmaf(a.z, b.z, fmaf(a.w, b.w, acc))));
}

// ======================= Kernel 0: Qh = query @ Wq + bq ======================
constexpr int K0_BLK_PTS = 128;
constexpr int K0_THREADS = 256;
constexpr int K0_SMEM    = (64 * 256 + K0_BLK_PTS * 64) * 4;   // 96 KB

__global__ __launch_bounds__(K0_THREADS, 1)
void qproj_kernel(const float* __restrict__ query, const float* __restrict__ Wq,
                  const float* __restrict__ bq)
{
    extern __shared__ float sm[];
    float* wq = sm;              // [64][256]
    float* q  = sm + 64 * 256;   // [128][64]
    const int t = threadIdx.x;

    for (int i = t; i < 4096; i += K0_THREADS)
        ((float4*)wq)[i] = ((const float4*)Wq)[i];
    const float4* qsrc = (const float4*)(query + (size_t)blockIdx.x * K0_BLK_PTS * 64);
    for (int i = t; i < K0_BLK_PTS * 16; i += K0_THREADS)
        ((float4*)q)[i] = qsrc[i];
    __syncthreads();

    const int c = t;             // output channel 0..255
    const float bqc = bq[c];
    for (int p0 = 0; p0 < K0_BLK_PTS; p0 += 4) {
        float a0 = bqc, a1 = bqc, a2 = bqc, a3 = bqc;
        #pragma unroll
        for (int f4 = 0; f4 < 16; ++f4) {
            float4 q0 = *(const float4*)(q + (p0 + 0) * 64 + f4 * 4);
            float4 q1 = *(const float4*)(q + (p0 + 1) * 64 + f4 * 4);
            float4 q2 = *(const float4*)(q + (p0 + 2) * 64 + f4 * 4);
            float4 q3 = *(const float4*)(q + (p0 + 3) * 64 + f4 * 4);
            float w0 = wq[(f4 * 4 + 0) * 256 + c];
            float w1 = wq[(f4 * 4 + 1) * 256 + c];
            float w2 = wq[(f4 * 4 + 2) * 256 + c];
            float w3 = wq[(f4 * 4 + 3) * 256 + c];
            a0 = fmaf(q0.x, w0, fmaf(q0.y, w1, fmaf(q0.z, w2, fmaf(q0.w, w3, a0))));
            a1 = fmaf(q1.x, w0, fmaf(q1.y, w1, fmaf(q1.z, w2, fmaf(q1.w, w3, a1))));
            a2 = fmaf(q2.x, w0, fmaf(q2.y, w1, fmaf(q2.z, w2, fmaf(q2.w, w3, a2))));
            a3 = fmaf(q3.x, w0, fmaf(q3.y, w1, fmaf(q3.z, w2, fmaf(q3.w, w3, a3))));
        }
        size_t o = ((size_t)blockIdx.x * K0_BLK_PTS + p0) * 256 + c;
        g_Qh[o]       = a0;
        g_Qh[o + 256] = a1;
        g_Qh[o + 512] = a2;
        g_Qh[o + 768] = a3;
    }
}

// ============================== Main kernel ==================================
// smem layout (floats)
constexpr int O_WK  = 0;                     // 64*260
constexpr int O_WV  = O_WK + 64 * 260;       // 64*260
constexpr int O_KP  = O_WV + 64 * 260;       // 32*260
constexpr int O_VP  = O_KP + 32 * 260;       // 32*260
constexpr int O_INP = O_VP + 32 * 260;       // 2 * 32*68 (double buffer)
constexpr int O_QH  = O_INP + 2 * 32 * 68;   // 2 * 256
constexpr int O_W   = O_QH + 2 * 256;        // 512
constexpr int O_B   = O_W + 512;             // bk(256) | bv(256)
constexpr int SMEM_FLOATS = O_B + 512;       // 55808 -> 223232 B
constexpr int SMEM_BYTES  = SMEM_FLOATS * 4;

__device__ __forceinline__ void prefetch_point(float* sm, int t, int pt, int buf,
                                               const float* inp) {
    // inp tile: 32x64 floats -> 512 cp16, one per thread
    int k = t >> 4, cq = t & 15;
    cp16(sm + O_INP + buf * (32 * 68) + k * 68 + cq * 4,
         inp + (size_t)pt * 2048 + k * 64 + cq * 4);
    // Qh row: 256 floats -> 64 cp16
    if (t < 64)
        cp16(sm + O_QH + buf * 256 + t * 4, g_Qh + (size_t)pt * 256 + t * 4);
}

__global__ __launch_bounds__(THREADS, 1)
void attn_main_kernel(const float* __restrict__ inp,
                      const float* __restrict__ Wk, const float* __restrict__ bk,
                      const float* __restrict__ Wv, const float* __restrict__ bv,
                      float* __restrict__ out)
{
    extern __shared__ float sm[];
    const int t = threadIdx.x;
    const int base0 = blockIdx.x * PPB;

    // prefetch first point before weight staging (overlap global latency)
    {
        int p0 = base0 < PTS ? base0 : PTS - 1;
        prefetch_point(sm, t, p0, 0, inp);
        cp_commit();
    }

    // stage Wk / Wv (padded stride 260: 260/4=65 odd -> conflict-free f4)
    for (int i = t; i < 4096; i += THREADS) {
        int f = i >> 6, cq = i & 63;
        *(float4*)(sm + O_WK + f * 260 + cq * 4) = ((const float4*)Wk)[i];
        *(float4*)(sm + O_WV + f * 260 + cq * 4) = ((const float4*)Wv)[i];
    }
    if (t < 256) { sm[O_B + t] = bk[t]; sm[O_B + 256 + t] = bv[t]; }
    __syncthreads();

    const int kgrp = t >> 6;          // 0..7  -> k rows kgrp*4 .. +3
    const int c0   = (t & 63) * 4;    // 0..252

    for (int r = 0; r < PPB; ++r) {
        int pt  = base0 + r;     if (pt  >= PTS) pt  = PTS - 1;
        int ptn = base0 + r + 1; if (ptn >= PTS) ptn = PTS - 1;
        const int buf = r & 1;

        // prefetch next point into the other buffer
        prefetch_point(sm, t, ptn, buf ^ 1, inp);
        cp_commit();

        cp_wait<1>();        // current point's data resident
        __syncthreads();

        // ---- P1: KP = inp@Wk + bk ; VP = inp@Wv + bv  (32x256 each) ----
        {
            float4 kp[4], vp[4];
            float4 bk4 = *(const float4*)(sm + O_B + c0);
            float4 bv4 = *(const float4*)(sm + O_B + 256 + c0);
            #pragma unroll
            for (int i = 0; i < 4; ++i) { kp[i] = bk4; vp[i] = bv4; }

            const float* inpP = sm + O_INP + buf * (32 * 68) + kgrp * 4 * 68;
            #pragma unroll
            for (int f4 = 0; f4 < 16; ++f4) {
                float x[4][4];
                *(float4*)x[0] = *(const float4*)(inpP + 0 * 68 + f4 * 4);
                *(float4*)x[1] = *(const float4*)(inpP + 1 * 68 + f4 * 4);
                *(float4*)x[2] = *(const float4*)(inpP + 2 * 68 + f4 * 4);
                *(float4*)x[3] = *(const float4*)(inpP + 3 * 68 + f4 * 4);
                #pragma unroll
                for (int ff = 0; ff < 4; ++ff) {
                    int f = f4 * 4 + ff;
                    float4 wk = *(const float4*)(sm + O_WK + f * 260 + c0);
                    float4 wv = *(const float4*)(sm + O_WV + f * 260 + c0);
                    #pragma unroll
                    for (int kk = 0; kk < 4; ++kk) {
                        float xv = x[kk][ff];
                        kp[kk].x = fmaf(xv, wk.x, kp[kk].x);
                        kp[kk].y = fmaf(xv, wk.y, kp[kk].y);
                        kp[kk].z = fmaf(xv, wk.z, kp[kk].z);
                        kp[kk].w = fmaf(xv, wk.w, kp[kk].w);
                        vp[kk].x = fmaf(xv, wv.x, vp[kk].x);
                        vp[kk].y = fmaf(xv, wv.y, vp[kk].y);
                        vp[kk].z = fmaf(xv, wv.z, vp[kk].z);
                        vp[kk].w = fmaf(xv, wv.w, vp[kk].w);
                    }
                }
            }
            #pragma unroll
            for (int kk = 0; kk < 4; ++kk) {
                *(float4*)(sm + O_KP + (kgrp * 4 + kk) * 260 + c0) = kp[kk];
                *(float4*)(sm + O_VP + (kgrp * 4 + kk) * 260 + c0) = vp[kk];
            }
        }
        __syncthreads();

        // ---- P2: scores + softmax. warp = head h, lane = k ----
        {
            const int h = t >> 5, k = t & 31;
            const int nb = 2 * h + (k >> 4), kk = k & 15;
            const float* kpP = sm + O_KP + nb * 260 + kk * 16;
            const float* qP  = sm + O_QH + buf * 256 + h * 16;
            float s = 0.f;
            #pragma unroll
            for (int d4 = 0; d4 < 4; ++d4)
                s = dot4(*(const float4*)(qP + d4 * 4),
                         *(const float4*)(kpP + d4 * 4), s);
            s *= 0.25f;                     // 1/sqrt(D)
            float m = s;
            #pragma unroll
            for (int off = 16; off; off >>= 1)
                m = fmaxf(m, __shfl_xor_sync(FULLMASK, m, off));
            float e = __expf(s - m);
            float ssum = e;
            #pragma unroll
            for (int off = 16; off; off >>= 1)
                ssum += __shfl_xor_sync(FULLMASK, ssum, off);
            sm[O_W + h * 32 + k] = e * __frcp_rn(ssum);
        }
        __syncthreads();

        // ---- P3: out[h*16+d] = sum_k w[h,k] * VP[2h+(k>>4), (k&15)*16+d] ----
        if (t < 256) {
            const int h = t >> 4, d = t & 15;
            const float* wP  = sm + O_W + h * 32;
            const float* vpP = sm + O_VP + 2 * h * 260 + d;
            float acc = 0.f;
            #pragma unroll
            for (int k = 0; k < 32; ++k)
                acc = fmaf(wP[k], vpP[(k >> 4) * 260 + (k & 15) * 16], acc);
            out[(size_t)pt * 256 + t] = acc;
        }
        // no barrier needed here: buf overwrite is gated by next iter's barrier
    }
}

// ================================ launch =====================================
extern "C" void kernel_launch(void* const* d_in, const int* in_sizes, int n_in,
                              void* d_out, int out_size) {
    const float* inp   = (const float*)d_in[0];
    const float* query = (const float*)d_in[1];
    const float* Wq    = (const float*)d_in[2];
    const float* bq    = (const float*)d_in[3];
    const float* Wk    = (const float*)d_in[4];
    const float* bk    = (const float*)d_in[5];
    const float* Wv    = (const float*)d_in[6];
    const float* bv    = (const float*)d_in[7];
    float* out = (float*)d_out;

    cudaFuncSetAttribute(qproj_kernel,
                         cudaFuncAttributeMaxDynamicSharedMemorySize, K0_SMEM);
    cudaFuncSetAttribute(attn_main_kernel,
                         cudaFuncAttributeMaxDynamicSharedMemorySize, SMEM_BYTES);

    qproj_kernel<<<PTS / K0_BLK_PTS, K0_THREADS, K0_SMEM>>>(query, Wq, bq);
    attn_main_kernel<<<GRID, THREADS, SMEM_BYTES>>>(inp, Wk, bk, Wv, bv, out);
}

// round 3
// speedup vs baseline: 1.0004x; 1.0004x over previous
#include <cuda_runtime.h>
#include <cstdint>
#include <cstddef>

// ---------------------------------------------------------------------------
// AttentionLayer: B=4, N=4096, Kn=32, F=64, H=16, D=16 (fp32)
//
// Faithful-reshape semantics:
//   K[h,k,d] = KP[2h + (k>>4), (k&15)*16 + d],  KP = inp @ Wk + bk  [32 x 256]
//   V[h,k,d] = VP[2h + (k>>4), (k&15)*16 + d],  VP = inp @ Wv + bv
//   s[h,k]   = 0.25 * Q_h . K[h,k,:]  ; w = softmax_k(s)
//   out[h*16+d] = sum_k w[h,k] * V[h,k,d]
// Qh = query @ Wq + bq precomputed by a small kernel into global scratch.
// ---------------------------------------------------------------------------

#define FULLMASK 0xffffffffu

constexpr int PTS     = 16384;
constexpr int GRID    = 152;
constexpr int PPB     = 108;          // 152*108 = 16416 >= 16384
constexpr int THREADS = 512;

__device__ float g_Qh[(size_t)PTS * 256];

__device__ __forceinline__ void cp16(void* dst_smem, const void* src) {
    uint32_t d = (uint32_t)__cvta_generic_to_shared(dst_smem);
    asm volatile("cp.async.ca.shared.global [%0], [%1], 16;" :: "r"(d), "l"(src) : "memory");
}
__device__ __forceinline__ void cp_commit() { asm volatile("cp.async.commit_group;" ::: "memory"); }
template <int N> __device__ __forceinline__ void cp_wait() {
    asm volatile("cp.async.wait_group %0;" :: "n"(N) : "memory");
}
__device__ __forceinline__ float dot4(float4 a, float4 b, float acc) {
    return fmaf(a.x, b.x, fmaf(a.y, b.y, fmaf(a.z, b.z, fmaf(a.w, b.w, acc))));
}

// ======================= Kernel 0: Qh = query @ Wq + bq ======================
constexpr int K0_BLK_PTS = 128;
constexpr int K0_THREADS = 256;
constexpr int K0_SMEM    = (64 * 256 + K0_BLK_PTS * 64) * 4;   // 96 KB

__global__ __launch_bounds__(K0_THREADS, 1)
void qproj_kernel(const float* __restrict__ query, const float* __restrict__ Wq,
                  const float* __restrict__ bq)
{
    extern __shared__ float sm[];
    float* wq = sm;              // [64][256]
    float* q  = sm + 64 * 256;   // [128][64]
    const int t = threadIdx.x;

    for (int i = t; i < 4096; i += K0_THREADS)
        ((float4*)wq)[i] = ((const float4*)Wq)[i];
    const float4* qsrc = (const float4*)(query + (size_t)blockIdx.x * K0_BLK_PTS * 64);
    for (int i = t; i < K0_BLK_PTS * 16; i += K0_THREADS)
        ((float4*)q)[i] = qsrc[i];
    __syncthreads();

    const int c = t;             // output channel 0..255
    const float bqc = bq[c];
    for (int p0 = 0; p0 < K0_BLK_PTS; p0 += 4) {
        float a0 = bqc, a1 = bqc, a2 = bqc, a3 = bqc;
        #pragma unroll
        for (int f4 = 0; f4 < 16; ++f4) {
            float4 q0 = *(const float4*)(q + (p0 + 0) * 64 + f4 * 4);
            float4 q1 = *(const float4*)(q + (p0 + 1) * 64 + f4 * 4);
            float4 q2 = *(const float4*)(q + (p0 + 2) * 64 + f4 * 4);
            float4 q3 = *(const float4*)(q + (p0 + 3) * 64 + f4 * 4);
            float w0 = wq[(f4 * 4 + 0) * 256 + c];
            float w1 = wq[(f4 * 4 + 1) * 256 + c];
            float w2 = wq[(f4 * 4 + 2) * 256 + c];
            float w3 = wq[(f4 * 4 + 3) * 256 + c];
            a0 = fmaf(q0.x, w0, fmaf(q0.y, w1, fmaf(q0.z, w2, fmaf(q0.w, w3, a0))));
            a1 = fmaf(q1.x, w0, fmaf(q1.y, w1, fmaf(q1.z, w2, fmaf(q1.w, w3, a1))));
            a2 = fmaf(q2.x, w0, fmaf(q2.y, w1, fmaf(q2.z, w2, fmaf(q2.w, w3, a2))));
            a3 = fmaf(q3.x, w0, fmaf(q3.y, w1, fmaf(q3.z, w2, fmaf(q3.w, w3, a3))));
        }
        size_t o = ((size_t)blockIdx.x * K0_BLK_PTS + p0) * 256 + c;
        g_Qh[o]       = a0;
        g_Qh[o + 256] = a1;
        g_Qh[o + 512] = a2;
        g_Qh[o + 768] = a3;
    }
}

// ============================== Main kernel ==================================
// smem layout (floats)
constexpr int O_WK  = 0;                     // 64*260
constexpr int O_WV  = O_WK + 64 * 260;       // 64*260
constexpr int O_KP  = O_WV + 64 * 260;       // 32*260
constexpr int O_VP  = O_KP + 32 * 260;       // 32*260
constexpr int O_INP = O_VP + 32 * 260;       // 2 * 32*68 (double buffer)
constexpr int O_QH  = O_INP + 2 * 32 * 68;   // 2 * 256
constexpr int O_W   = O_QH + 2 * 256;        // 512
constexpr int O_B   = O_W + 512;             // bk(256) | bv(256)
constexpr int SMEM_FLOATS = O_B + 512;       // 55808 -> 223232 B
constexpr int SMEM_BYTES  = SMEM_FLOATS * 4;

__device__ __forceinline__ void prefetch_point(float* sm, int t, int pt, int buf,
                                               const float* inp) {
    // inp tile: 32x64 floats -> 512 cp16, one per thread
    int k = t >> 4, cq = t & 15;
    cp16(sm + O_INP + buf * (32 * 68) + k * 68 + cq * 4,
         inp + (size_t)pt * 2048 + k * 64 + cq * 4);
    // Qh row: 256 floats -> 64 cp16
    if (t < 64)
        cp16(sm + O_QH + buf * 256 + t * 4, g_Qh + (size_t)pt * 256 + t * 4);
}

__global__ __launch_bounds__(THREADS, 1)
void attn_main_kernel(const float* __restrict__ inp,
                      const float* __restrict__ Wk, const float* __restrict__ bk,
                      const float* __restrict__ Wv, const float* __restrict__ bv,
                      float* __restrict__ out)
{
    extern __shared__ float sm[];
    const int t = threadIdx.x;
    const int base0 = blockIdx.x * PPB;

    // prefetch first point before weight staging (overlap global latency)
    {
        int p0 = base0 < PTS ? base0 : PTS - 1;
        prefetch_point(sm, t, p0, 0, inp);
        cp_commit();
    }

    // stage Wk / Wv (padded stride 260: 260/4=65 odd -> conflict-free f4)
    for (int i = t; i < 4096; i += THREADS) {
        int f = i >> 6, cq = i & 63;
        *(float4*)(sm + O_WK + f * 260 + cq * 4) = ((const float4*)Wk)[i];
        *(float4*)(sm + O_WV + f * 260 + cq * 4) = ((const float4*)Wv)[i];
    }
    if (t < 256) { sm[O_B + t] = bk[t]; sm[O_B + 256 + t] = bv[t]; }
    __syncthreads();

    const int kgrp = t >> 6;          // 0..7  -> k rows kgrp*4 .. +3
    const int c0   = (t & 63) * 4;    // 0..252

    for (int r = 0; r < PPB; ++r) {
        int pt  = base0 + r;     if (pt  >= PTS) pt  = PTS - 1;
        int ptn = base0 + r + 1; if (ptn >= PTS) ptn = PTS - 1;
        const int buf = r & 1;

        // prefetch next point into the other buffer
        prefetch_point(sm, t, ptn, buf ^ 1, inp);
        cp_commit();

        cp_wait<1>();        // current point's data resident
        __syncthreads();

        // ---- P1: KP = inp@Wk + bk ; VP = inp@Wv + bv  (32x256 each) ----
        {
            float4 kp[4], vp[4];
            float4 bk4 = *(const float4*)(sm + O_B + c0);
            float4 bv4 = *(const float4*)(sm + O_B + 256 + c0);
            #pragma unroll
            for (int i = 0; i < 4; ++i) { kp[i] = bk4; vp[i] = bv4; }

            const float* inpP = sm + O_INP + buf * (32 * 68) + kgrp * 4 * 68;
            #pragma unroll
            for (int f4 = 0; f4 < 16; ++f4) {
                float x[4][4];
                *(float4*)x[0] = *(const float4*)(inpP + 0 * 68 + f4 * 4);
                *(float4*)x[1] = *(const float4*)(inpP + 1 * 68 + f4 * 4);
                *(float4*)x[2] = *(const float4*)(inpP + 2 * 68 + f4 * 4);
                *(float4*)x[3] = *(const float4*)(inpP + 3 * 68 + f4 * 4);
                #pragma unroll
                for (int ff = 0; ff < 4; ++ff) {
                    int f = f4 * 4 + ff;
                    float4 wk = *(const float4*)(sm + O_WK + f * 260 + c0);
                    float4 wv = *(const float4*)(sm + O_WV + f * 260 + c0);
                    #pragma unroll
                    for (int kk = 0; kk < 4; ++kk) {
                        float xv = x[kk][ff];
                        kp[kk].x = fmaf(xv, wk.x, kp[kk].x);
                        kp[kk].y = fmaf(xv, wk.y, kp[kk].y);
                        kp[kk].z = fmaf(xv, wk.z, kp[kk].z);
                        kp[kk].w = fmaf(xv, wk.w, kp[kk].w);
                        vp[kk].x = fmaf(xv, wv.x, vp[kk].x);
                        vp[kk].y = fmaf(xv, wv.y, vp[kk].y);
                        vp[kk].z = fmaf(xv, wv.z, vp[kk].z);
                        vp[kk].w = fmaf(xv, wv.w, vp[kk].w);
                    }
                }
            }
            #pragma unroll
            for (int kk = 0; kk < 4; ++kk) {
                *(float4*)(sm + O_KP + (kgrp * 4 + kk) * 260 + c0) = kp[kk];
                *(float4*)(sm + O_VP + (kgrp * 4 + kk) * 260 + c0) = vp[kk];
            }
        }
        __syncthreads();

        // ---- P2: scores + softmax. warp = head h, lane = k ----
        {
            const int h = t >> 5, k = t & 31;
            const int nb = 2 * h + (k >> 4), kk = k & 15;
            const float* kpP = sm + O_KP + nb * 260 + kk * 16;
            const float* qP  = sm + O_QH + buf * 256 + h * 16;
            float s = 0.f;
            #pragma unroll
            for (int d4 = 0; d4 < 4; ++d4)
                s = dot4(*(const float4*)(qP + d4 * 4),
                         *(const float4*)(kpP + d4 * 4), s);
            s *= 0.25f;                     // 1/sqrt(D)
            float m = s;
            #pragma unroll
            for (int off = 16; off; off >>= 1)
                m = fmaxf(m, __shfl_xor_sync(FULLMASK, m, off));
            float e = __expf(s - m);
            float ssum = e;
            #pragma unroll
            for (int off = 16; off; off >>= 1)
                ssum += __shfl_xor_sync(FULLMASK, ssum, off);
            sm[O_W + h * 32 + k] = e * __frcp_rn(ssum);
        }
        __syncthreads();

        // ---- P3: out[h*16+d] = sum_k w[h,k] * VP[2h+(k>>4), (k&15)*16+d] ----
        if (t < 256) {
            const int h = t >> 4, d = t & 15;
            const float* wP  = sm + O_W + h * 32;
            const float* vpP = sm + O_VP + 2 * h * 260 + d;
            float acc = 0.f;
            #pragma unroll
            for (int k = 0; k < 32; ++k)
                acc = fmaf(wP[k], vpP[(k >> 4) * 260 + (k & 15) * 16], acc);
            out[(size_t)pt * 256 + t] = acc;
        }
        // no barrier needed here: buf overwrite is gated by next iter's barrier
    }
}

// ================================ launch =====================================
extern "C" void kernel_launch(void* const* d_in, const int* in_sizes, int n_in,
                              void* d_out, int out_size) {
    const float* inp   = (const float*)d_in[0];
    const float* query = (const float*)d_in[1];
    const float* Wq    = (const float*)d_in[2];
    const float* bq    = (const float*)d_in[3];
    const float* Wk    = (const float*)d_in[4];
    const float* bk    = (const float*)d_in[5];
    const float* Wv    = (const float*)d_in[6];
    const float* bv    = (const float*)d_in[7];
    float* out = (float*)d_out;

    cudaFuncSetAttribute(qproj_kernel,
                         cudaFuncAttributeMaxDynamicSharedMemorySize, K0_SMEM);
    cudaFuncSetAttribute(attn_main_kernel,
                         cudaFuncAttributeMaxDynamicSharedMemorySize, SMEM_BYTES);

    qproj_kernel<<<PTS / K0_BLK_PTS, K0_THREADS, K0_SMEM>>>(query, Wq, bq);
    attn_main_kernel<<<GRID, THREADS, SMEM_BYTES>>>(inp, Wk, bk, Wv, bv, out);
}

// round 8
// speedup vs baseline: 2.1572x; 2.1563x over previous
#include <cuda_runtime.h>
#include <cstdint>
#include <cstddef>

// ---------------------------------------------------------------------------
// AttentionLayer B=4,N=4096,Kn=32,F=64,H=16,D=16 (fp32 in/out)
//   KP = inp@Wk + bk [32x256], VP = inp@Wv + bv
//   K[h,k,d] = KP[2h+(k>>4), (k&15)*16+d]  (same for V)
//   s = 0.25*Qh_h.K ; w = softmax_k ; out = sum_k w*V
// P1 projections on mma.sync.m16n8k8 tf32 (sm_103-legal tensor path).
// Qh = query@Wq + bq in full fp32 (kernel 0). Biases added in fp32.
// ---------------------------------------------------------------------------

#define FULLMASK 0xffffffffu

constexpr int PTS     = 16384;
constexpr int GRID    = 152;
constexpr int PPB     = 108;
constexpr int THREADS = 512;

__device__ float g_Qh[(size_t)PTS * 256];

// smem offsets (floats)
constexpr int O_WKT = 0;                    // Wk^T [256 n][68] = 17408
constexpr int O_WVT = 17408;                // Wv^T
constexpr int O_KP  = 34816;                // [32][260] = 8320
constexpr int O_VP  = 43136;                // [32][260]
constexpr int O_INP = 51456;                // 2 x [32][68] = 4352
constexpr int O_QH  = 55808;                // 2 x 256
constexpr int O_W   = 56320;                // [16][32]
constexpr int O_B   = 56832;                // bk(256) | bv(256)
constexpr int SMEM_FLOATS = 57344;          // 229376 B
constexpr int SMEM_BYTES  = SMEM_FLOATS * 4;

__device__ __forceinline__ void cp16(void* dst_smem, const void* src) {
    uint32_t d = (uint32_t)__cvta_generic_to_shared(dst_smem);
    asm volatile("cp.async.ca.shared.global [%0], [%1], 16;" :: "r"(d), "l"(src) : "memory");
}
__device__ __forceinline__ void cp_commit() { asm volatile("cp.async.commit_group;" ::: "memory"); }
template <int N> __device__ __forceinline__ void cp_wait() {
    asm volatile("cp.async.wait_group %0;" :: "n"(N) : "memory");
}
__device__ __forceinline__ float dot4(float4 a, float4 b, float acc) {
    return fmaf(a.x, b.x, fmaf(a.y, b.y, fmaf(a.z, b.z, fmaf(a.w, b.w, acc))));
}
__device__ __forceinline__ uint32_t cvt_tf32(float x) {
    uint32_t u; asm("cvt.rna.tf32.f32 %0, %1;" : "=r"(u) : "f"(x)); return u;
}
__device__ __forceinline__ void mma_tf32(float c[4], const uint32_t a[4], const uint32_t b[2]) {
    asm volatile(
        "mma.sync.aligned.m16n8k8.row.col.f32.tf32.tf32.f32 "
        "{%0,%1,%2,%3}, {%4,%5,%6,%7}, {%8,%9}, {%0,%1,%2,%3};"
        : "+f"(c[0]), "+f"(c[1]), "+f"(c[2]), "+f"(c[3])
        : "r"(a[0]), "r"(a[1]), "r"(a[2]), "r"(a[3]), "r"(b[0]), "r"(b[1]));
}

// ===================== Kernel 0: Qh = query @ Wq + bq (fp32) ================
constexpr int K0_BLK  = 64;
constexpr int K0_SMEM = (64 * 256 + K0_BLK * 64) * 4;   // 80 KB -> 2 CTA/SM

__global__ __launch_bounds__(256, 2)
void qproj_kernel(const float* __restrict__ query, const float* __restrict__ Wq,
                  const float* __restrict__ bq)
{
    extern __shared__ float sm[];
    float* wq = sm;
    float* q  = sm + 64 * 256;
    const int t = threadIdx.x;

    for (int i = t; i < 4096; i += 256)
        ((float4*)wq)[i] = __ldg((const float4*)Wq + i);
    const float4* qsrc = (const float4*)(query + (size_t)blockIdx.x * K0_BLK * 64);
    for (int i = t; i < K0_BLK * 16; i += 256)
        ((float4*)q)[i] = __ldg(qsrc + i);
    __syncthreads();

    const int c = t;
    const float bqc = bq[c];
    for (int p0 = 0; p0 < K0_BLK; p0 += 4) {
        float a0 = bqc, a1 = bqc, a2 = bqc, a3 = bqc;
        #pragma unroll
        for (int f4 = 0; f4 < 16; ++f4) {
            float4 q0 = *(const float4*)(q + (p0 + 0) * 64 + f4 * 4);
            float4 q1 = *(const float4*)(q + (p0 + 1) * 64 + f4 * 4);
            float4 q2 = *(const float4*)(q + (p0 + 2) * 64 + f4 * 4);
            float4 q3 = *(const float4*)(q + (p0 + 3) * 64 + f4 * 4);
            float w0 = wq[(f4 * 4 + 0) * 256 + c];
            float w1 = wq[(f4 * 4 + 1) * 256 + c];
            float w2 = wq[(f4 * 4 + 2) * 256 + c];
            float w3 = wq[(f4 * 4 + 3) * 256 + c];
            a0 = fmaf(q0.x, w0, fmaf(q0.y, w1, fmaf(q0.z, w2, fmaf(q0.w, w3, a0))));
            a1 = fmaf(q1.x, w0, fmaf(q1.y, w1, fmaf(q1.z, w2, fmaf(q1.w, w3, a1))));
            a2 = fmaf(q2.x, w0, fmaf(q2.y, w1, fmaf(q2.z, w2, fmaf(q2.w, w3, a2))));
            a3 = fmaf(q3.x, w0, fmaf(q3.y, w1, fmaf(q3.z, w2, fmaf(q3.w, w3, a3))));
        }
        size_t o = ((size_t)blockIdx.x * K0_BLK + p0) * 256 + c;
        g_Qh[o] = a0; g_Qh[o + 256] = a1; g_Qh[o + 512] = a2; g_Qh[o + 768] = a3;
    }
}

// ============================== Main kernel ==================================
__device__ __forceinline__ void prefetch_point(float* sm, int t, int pt, int buf,
                                               const float* inp) {
    // inp tile: 32x64 floats -> 512 cp16, one per thread
    int k = t >> 4, cq = t & 15;
    cp16(sm + O_INP + buf * (32 * 68) + k * 68 + cq * 4,
         inp + (size_t)pt * 2048 + k * 64 + cq * 4);
    // Qh row: 256 floats -> 64 cp16
    if (t < 64)
        cp16(sm + O_QH + buf * 256 + t * 4, g_Qh + (size_t)pt * 256 + t * 4);
}

__global__ __launch_bounds__(THREADS, 1)
void attn_main_kernel(const float* __restrict__ inp,
                      const float* __restrict__ Wk, const float* __restrict__ bk,
                      const float* __restrict__ Wv, const float* __restrict__ bv,
                      float* __restrict__ out)
{
    extern __shared__ float sm[];
    const int t   = threadIdx.x;
    const int wid = t >> 5;
    const int ln  = t & 31;
    const int base0 = blockIdx.x * PPB;

    // prefetch first point (overlaps weight staging)
    {
        int p0 = base0 < PTS ? base0 : PTS - 1;
        prefetch_point(sm, t, p0, 0, inp);
        cp_commit();
    }

    // stage Wk^T / Wv^T as [256 n][68 f] (stride 68 -> (4r+c)%32 unique: conflict-free)
    for (int i = t; i < 4096; i += THREADS) {       // i over [64 f][64 n4]
        int f = i >> 6, n0 = (i & 63) * 4;
        float4 a = __ldg((const float4*)Wk + i);
        sm[O_WKT + (n0 + 0) * 68 + f] = a.x;
        sm[O_WKT + (n0 + 1) * 68 + f] = a.y;
        sm[O_WKT + (n0 + 2) * 68 + f] = a.z;
        sm[O_WKT + (n0 + 3) * 68 + f] = a.w;
        float4 b = __ldg((const float4*)Wv + i);
        sm[O_WVT + (n0 + 0) * 68 + f] = b.x;
        sm[O_WVT + (n0 + 1) * 68 + f] = b.y;
        sm[O_WVT + (n0 + 2) * 68 + f] = b.z;
        sm[O_WVT + (n0 + 3) * 68 + f] = b.w;
    }
    if (t < 256) { sm[O_B + t] = bk[t]; sm[O_B + 256 + t] = bv[t]; }
    __syncthreads();

    // ---- hoist B-fragments (weights) into registers: constant across rounds ----
    // warp wid: proj = wid>>3 (0=KP,1=VP), n-range = (wid&7)*32 .. +31
    const int proj = wid >> 3;
    const int nb_  = (wid & 7) * 32;
    const float* WT  = sm + (proj ? O_WVT : O_WKT);
    float* OUT = sm + (proj ? O_VP : O_KP);
    uint32_t bfr[2][8][2][2];        // [chunk16][kstep][j8][2]
    float2   b2[2][2];               // bias pairs per (chunk, j)
    #pragma unroll
    for (int ch = 0; ch < 2; ++ch) {
        #pragma unroll
        for (int s = 0; s < 8; ++s) {
            #pragma unroll
            for (int j = 0; j < 2; ++j) {
                int n = nb_ + ch * 16 + j * 8 + (ln >> 2);
                int f = s * 8 + (ln & 3);
                bfr[ch][s][j][0] = cvt_tf32(WT[n * 68 + f]);
                bfr[ch][s][j][1] = cvt_tf32(WT[n * 68 + f + 4]);
            }
        }
        #pragma unroll
        for (int j = 0; j < 2; ++j) {
            int col = nb_ + ch * 16 + j * 8 + 2 * (ln & 3);
            b2[ch][j] = make_float2(sm[O_B + proj * 256 + col],
                                    sm[O_B + proj * 256 + col + 1]);
        }
    }

    for (int r = 0; r < PPB; ++r) {
        int pt  = base0 + r;     if (pt  >= PTS) pt  = PTS - 1;
        int ptn = base0 + r + 1; if (ptn >= PTS) ptn = PTS - 1;
        const int buf = r & 1;

        prefetch_point(sm, t, ptn, buf ^ 1, inp);
        cp_commit();

        cp_wait<1>();        // current point resident
        __syncthreads();

        // ---- P1: KP/VP via mma.sync tf32. M=32, per-warp N=32, K=64 ----
        {
            float c[2][2][2][4];             // [mi][ch][j][4]
            #pragma unroll
            for (int mi = 0; mi < 2; ++mi)
                #pragma unroll
                for (int ch = 0; ch < 2; ++ch)
                    #pragma unroll
                    for (int j = 0; j < 2; ++j)
                        #pragma unroll
                        for (int q = 0; q < 4; ++q) c[mi][ch][j][q] = 0.f;

            const float* inpP = sm + O_INP + buf * (32 * 68);
            const int r0 = ln >> 2, f0 = ln & 3;
            #pragma unroll
            for (int s = 0; s < 8; ++s) {
                uint32_t a[2][4];
                const int cc = s * 8 + f0;
                a[0][0] = cvt_tf32(inpP[(r0 +  0) * 68 + cc]);
                a[0][1] = cvt_tf32(inpP[(r0 +  8) * 68 + cc]);
                a[0][2] = cvt_tf32(inpP[(r0 +  0) * 68 + cc + 4]);
                a[0][3] = cvt_tf32(inpP[(r0 +  8) * 68 + cc + 4]);
                a[1][0] = cvt_tf32(inpP[(r0 + 16) * 68 + cc]);
                a[1][1] = cvt_tf32(inpP[(r0 + 24) * 68 + cc]);
                a[1][2] = cvt_tf32(inpP[(r0 + 16) * 68 + cc + 4]);
                a[1][3] = cvt_tf32(inpP[(r0 + 24) * 68 + cc + 4]);
                #pragma unroll
                for (int mi = 0; mi < 2; ++mi)
                    #pragma unroll
                    for (int ch = 0; ch < 2; ++ch)
                        #pragma unroll
                        for (int j = 0; j < 2; ++j)
                            mma_tf32(c[mi][ch][j], a[mi], bfr[ch][s][j]);
            }
            // store with bias (fp32 exact)
            #pragma unroll
            for (int mi = 0; mi < 2; ++mi) {
                const int row = mi * 16 + (ln >> 2);
                #pragma unroll
                for (int ch = 0; ch < 2; ++ch)
                    #pragma unroll
                    for (int j = 0; j < 2; ++j) {
                        const int col = nb_ + ch * 16 + j * 8 + 2 * (ln & 3);
                        float2 bb = b2[ch][j];
                        *(float2*)(OUT + row * 260 + col) =
                            make_float2(c[mi][ch][j][0] + bb.x, c[mi][ch][j][1] + bb.y);
                        *(float2*)(OUT + (row + 8) * 260 + col) =
                            make_float2(c[mi][ch][j][2] + bb.x, c[mi][ch][j][3] + bb.y);
                    }
            }
        }
        __syncthreads();

        // ---- P2: scores + softmax. warp = head h, lane = k ----
        {
            const int h = wid, k = ln;
            const int nb = 2 * h + (k >> 4), kk = k & 15;
            const float* kpP = sm + O_KP + nb * 260 + kk * 16;
            const float* qP  = sm + O_QH + buf * 256 + h * 16;
            float s = 0.f;
            #pragma unroll
            for (int d4 = 0; d4 < 4; ++d4)
                s = dot4(*(const float4*)(qP + d4 * 4),
                         *(const float4*)(kpP + d4 * 4), s);
            s *= 0.25f;                     // 1/sqrt(D)
            float m = s;
            #pragma unroll
            for (int off = 16; off; off >>= 1)
                m = fmaxf(m, __shfl_xor_sync(FULLMASK, m, off));
            float e = __expf(s - m);
            float ssum = e;
            #pragma unroll
            for (int off = 16; off; off >>= 1)
                ssum += __shfl_xor_sync(FULLMASK, ssum, off);
            sm[O_W + h * 32 + k] = e * __frcp_rn(ssum);
        }
        __syncthreads();

        // ---- P3: out[h*16+d] = sum_k w[h,k] * VP[2h+(k>>4), (k&15)*16+d] ----
        if (t < 256) {
            const int h = t >> 4, d = t & 15;
            const float* wP  = sm + O_W + h * 32;
            const float* vpP = sm + O_VP + 2 * h * 260 + d;
            float acc = 0.f;
            #pragma unroll
            for (int k = 0; k < 32; ++k)
                acc = fmaf(wP[k], vpP[(k >> 4) * 260 + (k & 15) * 16], acc);
            out[(size_t)pt * 256 + t] = acc;
        }
        // buf/KP/VP overwrite gated by next iteration's barrier
    }
}

// ================================ launch =====================================
extern "C" void kernel_launch(void* const* d_in, const int* in_sizes, int n_in,
                              void* d_out, int out_size) {
    const float* inp   = (const float*)d_in[0];
    const float* query = (const float*)d_in[1];
    const float* Wq    = (const float*)d_in[2];
    const float* bq    = (const float*)d_in[3];
    const float* Wk    = (const float*)d_in[4];
    const float* bk    = (const float*)d_in[5];
    const float* Wv    = (const float*)d_in[6];
    const float* bv    = (const float*)d_in[7];
    float* out = (float*)d_out;

    cudaFuncSetAttribute(qproj_kernel,
                         cudaFuncAttributeMaxDynamicSharedMemorySize, K0_SMEM);
    cudaFuncSetAttribute(attn_main_kernel,
                         cudaFuncAttributeMaxDynamicSharedMemorySize, SMEM_BYTES);

    qproj_kernel<<<PTS / K0_BLK, 256, K0_SMEM>>>(query, Wq, bq);
    attn_main_kernel<<<GRID, THREADS, SMEM_BYTES>>>(inp, Wk, bk, Wv, bv, out);
}

// round 9
// speedup vs baseline: 2.2447x; 1.0406x over previous
#include <cuda_runtime.h>
#include <cuda_fp16.h>
#include <cstdint>
#include <cstddef>

// ---------------------------------------------------------------------------
// AttentionLayer B=4,N=4096,Kn=32,F=64,H=16,D=16 (fp32 in/out)
//   KP = inp@Wk + bk [32x256], VP = inp@Wv + bv
//   K[h,k,d] = KP[2h+(k>>4), (k&15)*16+d]  (same for V)
//   s = 0.25*Qh_h.K ; w = softmax_k ; out = sum_k w*V
// P1 projections via mma.sync.m16n8k16 fp16 (fp32 accum; fp16 mantissa == tf32).
// P2+P3 merged per-warp (weights stay in registers). Qh in fp32 (kernel 0).
// ---------------------------------------------------------------------------

#define FULLMASK 0xffffffffu

constexpr int PTS     = 16384;
constexpr int GRID    = 152;
constexpr int PPB     = 108;
constexpr int THREADS = 512;

__device__ float g_Qh[(size_t)PTS * 256];

// smem offsets (floats)
constexpr int O_WKT = 0;                    // Wk^T [256 n][68 f] = 17408
constexpr int O_WVT = 17408;                // Wv^T
constexpr int O_KP  = 34816;                // [32][260] = 8320
constexpr int O_VP  = 43136;                // [32][260]
constexpr int O_INP = 51456;                // 2 x [32][68] = 4352
constexpr int O_QH  = 55808;                // 2 x 256
constexpr int O_B   = 56320;                // bk(256) | bv(256)
constexpr int SMEM_FLOATS = 56832;          // 227328 B
constexpr int SMEM_BYTES  = SMEM_FLOATS * 4;

__device__ __forceinline__ void cp16(void* dst_smem, const void* src) {
    uint32_t d = (uint32_t)__cvta_generic_to_shared(dst_smem);
    asm volatile("cp.async.ca.shared.global [%0], [%1], 16;" :: "r"(d), "l"(src) : "memory");
}
__device__ __forceinline__ void cp_commit() { asm volatile("cp.async.commit_group;" ::: "memory"); }
template <int N> __device__ __forceinline__ void cp_wait() {
    asm volatile("cp.async.wait_group %0;" :: "n"(N) : "memory");
}
__device__ __forceinline__ float dot4(float4 a, float4 b, float acc) {
    return fmaf(a.x, b.x, fmaf(a.y, b.y, fmaf(a.z, b.z, fmaf(a.w, b.w, acc))));
}
__device__ __forceinline__ uint32_t pack_h2(float lo, float hi) {
    __half2 h = __floats2half2_rn(lo, hi);
    return *(uint32_t*)&h;
}
__device__ __forceinline__ void mma_f16(float c[4], const uint32_t a[4], const uint32_t b[2]) {
    asm volatile(
        "mma.sync.aligned.m16n8k16.row.col.f32.f16.f16.f32 "
        "{%0,%1,%2,%3}, {%4,%5,%6,%7}, {%8,%9}, {%0,%1,%2,%3};"
        : "+f"(c[0]), "+f"(c[1]), "+f"(c[2]), "+f"(c[3])
        : "r"(a[0]), "r"(a[1]), "r"(a[2]), "r"(a[3]), "r"(b[0]), "r"(b[1]));
}

// ===================== Kernel 0: Qh = query @ Wq + bq (fp32) ================
constexpr int K0_BLK  = 64;
constexpr int K0_SMEM = (64 * 256 + K0_BLK * 64) * 4;   // 80 KB -> 2 CTA/SM

__global__ __launch_bounds__(256, 2)
void qproj_kernel(const float* __restrict__ query, const float* __restrict__ Wq,
                  const float* __restrict__ bq)
{
    extern __shared__ float sm[];
    float* wq = sm;
    float* q  = sm + 64 * 256;
    const int t = threadIdx.x;

    for (int i = t; i < 4096; i += 256)
        ((float4*)wq)[i] = __ldg((const float4*)Wq + i);
    const float4* qsrc = (const float4*)(query + (size_t)blockIdx.x * K0_BLK * 64);
    for (int i = t; i < K0_BLK * 16; i += 256)
        ((float4*)q)[i] = __ldg(qsrc + i);
    __syncthreads();

    const int c = t;
    const float bqc = bq[c];
    for (int p0 = 0; p0 < K0_BLK; p0 += 4) {
        float a0 = bqc, a1 = bqc, a2 = bqc, a3 = bqc;
        #pragma unroll
        for (int f4 = 0; f4 < 16; ++f4) {
            float4 q0 = *(const float4*)(q + (p0 + 0) * 64 + f4 * 4);
            float4 q1 = *(const float4*)(q + (p0 + 1) * 64 + f4 * 4);
            float4 q2 = *(const float4*)(q + (p0 + 2) * 64 + f4 * 4);
            float4 q3 = *(const float4*)(q + (p0 + 3) * 64 + f4 * 4);
            float w0 = wq[(f4 * 4 + 0) * 256 + c];
            float w1 = wq[(f4 * 4 + 1) * 256 + c];
            float w2 = wq[(f4 * 4 + 2) * 256 + c];
            float w3 = wq[(f4 * 4 + 3) * 256 + c];
            a0 = fmaf(q0.x, w0, fmaf(q0.y, w1, fmaf(q0.z, w2, fmaf(q0.w, w3, a0))));
            a1 = fmaf(q1.x, w0, fmaf(q1.y, w1, fmaf(q1.z, w2, fmaf(q1.w, w3, a1))));
            a2 = fmaf(q2.x, w0, fmaf(q2.y, w1, fmaf(q2.z, w2, fmaf(q2.w, w3, a2))));
            a3 = fmaf(q3.x, w0, fmaf(q3.y, w1, fmaf(q3.z, w2, fmaf(q3.w, w3, a3))));
        }
        size_t o = ((size_t)blockIdx.x * K0_BLK + p0) * 256 + c;
        g_Qh[o] = a0; g_Qh[o + 256] = a1; g_Qh[o + 512] = a2; g_Qh[o + 768] = a3;
    }
}

// ============================== Main kernel ==================================
__device__ __forceinline__ void prefetch_point(float* sm, int t, int pt, int buf,
                                               const float* inp) {
    int k = t >> 4, cq = t & 15;
    cp16(sm + O_INP + buf * (32 * 68) + k * 68 + cq * 4,
         inp + (size_t)pt * 2048 + k * 64 + cq * 4);
    if (t < 64)
        cp16(sm + O_QH + buf * 256 + t * 4, g_Qh + (size_t)pt * 256 + t * 4);
}

__global__ __launch_bounds__(THREADS, 1)
void attn_main_kernel(const float* __restrict__ inp,
                      const float* __restrict__ Wk, const float* __restrict__ bk,
                      const float* __restrict__ Wv, const float* __restrict__ bv,
                      float* __restrict__ out)
{
    extern __shared__ float sm[];
    const int t   = threadIdx.x;
    const int wid = t >> 5;
    const int ln  = t & 31;
    const int base0 = blockIdx.x * PPB;

    // prefetch first point (overlaps weight staging)
    {
        int p0 = base0 < PTS ? base0 : PTS - 1;
        prefetch_point(sm, t, p0, 0, inp);
        cp_commit();
    }

    // stage Wk^T / Wv^T as [256 n][68 f]
    for (int i = t; i < 4096; i += THREADS) {       // i over [64 f][64 n4]
        int f = i >> 6, n0 = (i & 63) * 4;
        float4 a = __ldg((const float4*)Wk + i);
        sm[O_WKT + (n0 + 0) * 68 + f] = a.x;
        sm[O_WKT + (n0 + 1) * 68 + f] = a.y;
        sm[O_WKT + (n0 + 2) * 68 + f] = a.z;
        sm[O_WKT + (n0 + 3) * 68 + f] = a.w;
        float4 b = __ldg((const float4*)Wv + i);
        sm[O_WVT + (n0 + 0) * 68 + f] = b.x;
        sm[O_WVT + (n0 + 1) * 68 + f] = b.y;
        sm[O_WVT + (n0 + 2) * 68 + f] = b.z;
        sm[O_WVT + (n0 + 3) * 68 + f] = b.w;
    }
    if (t < 256) { sm[O_B + t] = bk[t]; sm[O_B + 256 + t] = bv[t]; }
    __syncthreads();

    // ---- hoist fp16 B-fragments: warp wid -> proj (wid>>3), n-range (wid&7)*32 ----
    const int proj = wid >> 3;
    const int nb_  = (wid & 7) * 32;
    const int r0 = ln >> 2;           // fragment row group
    const int cc = (ln & 3) * 2;      // fragment k/col pair base
    const float* WT = sm + (proj ? O_WVT : O_WKT);
    float* OUT = sm + (proj ? O_VP : O_KP);
    uint32_t bfr[4][4][2];            // [j(n8)][s(k16)][2]
    float2   b2[4];
    #pragma unroll
    for (int j = 0; j < 4; ++j) {
        const int n = nb_ + j * 8 + r0;
        #pragma unroll
        for (int s = 0; s < 4; ++s) {
            const int kb = s * 16 + cc;
            bfr[j][s][0] = pack_h2(WT[n * 68 + kb],     WT[n * 68 + kb + 1]);
            bfr[j][s][1] = pack_h2(WT[n * 68 + kb + 8], WT[n * 68 + kb + 9]);
        }
        const int col = nb_ + j * 8 + cc;
        b2[j] = make_float2(sm[O_B + proj * 256 + col],
                            sm[O_B + proj * 256 + col + 1]);
    }

    for (int r = 0; r < PPB; ++r) {
        int pt  = base0 + r;     if (pt  >= PTS) pt  = PTS - 1;
        int ptn = base0 + r + 1; if (ptn >= PTS) ptn = PTS - 1;
        const int buf = r & 1;

        prefetch_point(sm, t, ptn, buf ^ 1, inp);
        cp_commit();

        cp_wait<1>();        // current point resident
        __syncthreads();     // also gates KP/VP overwrite vs last round's readers

        // ---- P1: KP/VP via mma.sync m16n8k16 fp16. M=32, per-warp N=32, K=64 ----
        {
            float c[2][4][4];
            #pragma unroll
            for (int mi = 0; mi < 2; ++mi)
                #pragma unroll
                for (int j = 0; j < 4; ++j)
                    #pragma unroll
                    for (int q = 0; q < 4; ++q) c[mi][j][q] = 0.f;

            const float* inpP = sm + O_INP + buf * (32 * 68);
            #pragma unroll
            for (int s = 0; s < 4; ++s) {
                const int kb = s * 16 + cc;
                uint32_t a[2][4];
                #pragma unroll
                for (int mi = 0; mi < 2; ++mi) {
                    const int row = mi * 16 + r0;
                    float2 x0 = *(const float2*)(inpP + (row    ) * 68 + kb);
                    float2 x1 = *(const float2*)(inpP + (row + 8) * 68 + kb);
                    float2 x2 = *(const float2*)(inpP + (row    ) * 68 + kb + 8);
                    float2 x3 = *(const float2*)(inpP + (row + 8) * 68 + kb + 8);
                    a[mi][0] = pack_h2(x0.x, x0.y);
                    a[mi][1] = pack_h2(x1.x, x1.y);
                    a[mi][2] = pack_h2(x2.x, x2.y);
                    a[mi][3] = pack_h2(x3.x, x3.y);
                }
                #pragma unroll
                for (int mi = 0; mi < 2; ++mi)
                    #pragma unroll
                    for (int j = 0; j < 4; ++j)
                        mma_f16(c[mi][j], a[mi], bfr[j][s]);
            }
            // store with bias (fp32 exact)
            #pragma unroll
            for (int mi = 0; mi < 2; ++mi) {
                const int row = mi * 16 + r0;
                #pragma unroll
                for (int j = 0; j < 4; ++j) {
                    const int col = nb_ + j * 8 + cc;
                    const float2 bb = b2[j];
                    *(float2*)(OUT + row * 260 + col) =
                        make_float2(c[mi][j][0] + bb.x, c[mi][j][1] + bb.y);
                    *(float2*)(OUT + (row + 8) * 260 + col) =
                        make_float2(c[mi][j][2] + bb.x, c[mi][j][3] + bb.y);
                }
            }
        }
        __syncthreads();

        // ---- P2+P3 merged: warp = head h. scores -> softmax -> output ----
        {
            const int h = wid;
            // scores: lane = k
            const int nb = 2 * h + (ln >> 4), kk = ln & 15;
            const float* kpP = sm + O_KP + nb * 260 + kk * 16;
            const float* qP  = sm + O_QH + buf * 256 + h * 16;
            float s = 0.f;
            #pragma unroll
            for (int d4 = 0; d4 < 4; ++d4)
                s = dot4(*(const float4*)(qP + d4 * 4),
                         *(const float4*)(kpP + d4 * 4), s);
            s *= 0.25f;                     // 1/sqrt(D)
            float m = s;
            #pragma unroll
            for (int off = 16; off; off >>= 1)
                m = fmaxf(m, __shfl_xor_sync(FULLMASK, m, off));
            float e = __expf(s - m);
            float ssum = e;
            #pragma unroll
            for (int off = 16; off; off >>= 1)
                ssum += __shfl_xor_sync(FULLMASK, ssum, off);
            const float w = e * __frcp_rn(ssum);   // lane k holds w[h,k]

            // output: lane l = (half = l>>4 selects k-range, d = l&15)
            const int half = ln >> 4, d = ln & 15;
            const float* vrow = sm + O_VP + (2 * h + half) * 260 + d;
            float acc = 0.f;
            #pragma unroll
            for (int j = 0; j < 16; ++j) {
                const float wj = __shfl_sync(FULLMASK, w, half * 16 + j);
                acc = fmaf(wj, vrow[j * 16], acc);
            }
            acc += __shfl_xor_sync(FULLMASK, acc, 16);
            if (half == 0)
                out[(size_t)pt * 256 + h * 16 + d] = acc;
        }
        // next round's top barrier gates KP/VP/inp reuse
    }
}

// ================================ launch =====================================
extern "C" void kernel_launch(void* const* d_in, const int* in_sizes, int n_in,
                              void* d_out, int out_size) {
    const float* inp   = (const float*)d_in[0];
    const float* query = (const float*)d_in[1];
    const float* Wq    = (const float*)d_in[2];
    const float* bq    = (const float*)d_in[3];
    const float* Wk    = (const float*)d_in[4];
    const float* bk    = (const float*)d_in[5];
    const float* Wv    = (const float*)d_in[6];
    const float* bv    = (const float*)d_in[7];
    float* out = (float*)d_out;

    cudaFuncSetAttribute(qproj_kernel,
                         cudaFuncAttributeMaxDynamicSharedMemorySize, K0_SMEM);
    cudaFuncSetAttribute(attn_main_kernel,
                         cudaFuncAttributeMaxDynamicSharedMemorySize, SMEM_BYTES);

    qproj_kernel<<<PTS / K0_BLK, 256, K0_SMEM>>>(query, Wq, bq);
    attn_main_kernel<<<GRID, THREADS, SMEM_BYTES>>>(inp, Wk, bk, Wv, bv, out);
}

// round 10
// speedup vs baseline: 2.7672x; 1.2328x over previous
#include <cuda_runtime.h>
#include <cuda_fp16.h>
#include <cstdint>
#include <cstddef>

// ---------------------------------------------------------------------------
// AttentionLayer B=4,N=4096,Kn=32,F=64,H=16,D=16 (fp32 in/out)
//   KP = inp@Wk + bk [32x256], VP = inp@Wv + bv
//   K[h,k,d] = KP[2h+(k>>4), (k&15)*16+d]  (same for V)
//   s = 0.25*Qh_h.K ; w = softmax_k ; out = sum_k w*V
// P1 via mma.sync.m16n8k16 fp16 fed by ldmatrix from an fp16 inp tile
// (converted once at staging). Qh = query@Wq + bq in fp32 (kernel 0).
// ---------------------------------------------------------------------------

#define FULLMASK 0xffffffffu

constexpr int PTS     = 16384;
constexpr int GRID    = 152;
constexpr int PPB     = 108;
constexpr int THREADS = 512;

__device__ float g_Qh[(size_t)PTS * 256];

// smem offsets (floats)
constexpr int O_WKT = 0;                    // Wk^T [256 n][68 f] = 17408 (init only)
constexpr int O_WVT = 17408;                // Wv^T
constexpr int O_KP  = 34816;                // [32][260] fp32
constexpr int O_VP  = 43136;                // [32][260] fp32
constexpr int O_A16 = 51456;                // fp16 tile: 2 x [32][72] halfs = 2304 floats
constexpr int O_QH  = 53760;                // 2 x 256 fp32
constexpr int O_B   = 54272;                // bk(256) | bv(256)
constexpr int SMEM_FLOATS = 54784;          // 219136 B
constexpr int SMEM_BYTES  = SMEM_FLOATS * 4;

constexpr int A_TILE_BYTES = 32 * 144;      // 4608 B per buffer (row stride 144 B)

__device__ __forceinline__ float dot4(float4 a, float4 b, float acc) {
    return fmaf(a.x, b.x, fmaf(a.y, b.y, fmaf(a.z, b.z, fmaf(a.w, b.w, acc))));
}
__device__ __forceinline__ uint32_t pack_h2(float lo, float hi) {
    __half2 h = __floats2half2_rn(lo, hi);
    return *(uint32_t*)&h;
}
__device__ __forceinline__ void mma_f16(float c[4], const uint32_t a[4], const uint32_t b[2]) {
    asm volatile(
        "mma.sync.aligned.m16n8k16.row.col.f32.f16.f16.f32 "
        "{%0,%1,%2,%3}, {%4,%5,%6,%7}, {%8,%9}, {%0,%1,%2,%3};"
        : "+f"(c[0]), "+f"(c[1]), "+f"(c[2]), "+f"(c[3])
        : "r"(a[0]), "r"(a[1]), "r"(a[2]), "r"(a[3]), "r"(b[0]), "r"(b[1]));
}
__device__ __forceinline__ void ldmx4(uint32_t a[4], uint32_t addr) {
    asm volatile("ldmatrix.sync.aligned.m8n8.x4.shared.b16 {%0,%1,%2,%3}, [%4];"
                 : "=r"(a[0]), "=r"(a[1]), "=r"(a[2]), "=r"(a[3]) : "r"(addr));
}
__device__ __forceinline__ uint32_t smem_u32(const void* p) {
    uint32_t a;
    asm("{ .reg .u64 t; cvta.to.shared.u64 t, %1; cvt.u32.u64 %0, t; }" : "=r"(a) : "l"(p));
    return a;
}

// ===================== Kernel 0: Qh = query @ Wq + bq (fp32) ================
constexpr int K0_BLK  = 64;
constexpr int K0_SMEM = (64 * 256 + K0_BLK * 64) * 4;   // 80 KB -> 2 CTA/SM

__global__ __launch_bounds__(256, 2)
void qproj_kernel(const float* __restrict__ query, const float* __restrict__ Wq,
                  const float* __restrict__ bq)
{
    extern __shared__ float sm[];
    float* wq = sm;
    float* q  = sm + 64 * 256;
    const int t = threadIdx.x;

    for (int i = t; i < 4096; i += 256)
        ((float4*)wq)[i] = __ldg((const float4*)Wq + i);
    const float4* qsrc = (const float4*)(query + (size_t)blockIdx.x * K0_BLK * 64);
    for (int i = t; i < K0_BLK * 16; i += 256)
        ((float4*)q)[i] = __ldg(qsrc + i);
    __syncthreads();

    const int c = t;
    const float bqc = bq[c];
    for (int p0 = 0; p0 < K0_BLK; p0 += 4) {
        float a0 = bqc, a1 = bqc, a2 = bqc, a3 = bqc;
        #pragma unroll
        for (int f4 = 0; f4 < 16; ++f4) {
            float4 q0 = *(const float4*)(q + (p0 + 0) * 64 + f4 * 4);
            float4 q1 = *(const float4*)(q + (p0 + 1) * 64 + f4 * 4);
            float4 q2 = *(const float4*)(q + (p0 + 2) * 64 + f4 * 4);
            float4 q3 = *(const float4*)(q + (p0 + 3) * 64 + f4 * 4);
            float w0 = wq[(f4 * 4 + 0) * 256 + c];
            float w1 = wq[(f4 * 4 + 1) * 256 + c];
            float w2 = wq[(f4 * 4 + 2) * 256 + c];
            float w3 = wq[(f4 * 4 + 3) * 256 + c];
            a0 = fmaf(q0.x, w0, fmaf(q0.y, w1, fmaf(q0.z, w2, fmaf(q0.w, w3, a0))));
            a1 = fmaf(q1.x, w0, fmaf(q1.y, w1, fmaf(q1.z, w2, fmaf(q1.w, w3, a1))));
            a2 = fmaf(q2.x, w0, fmaf(q2.y, w1, fmaf(q2.z, w2, fmaf(q2.w, w3, a2))));
            a3 = fmaf(q3.x, w0, fmaf(q3.y, w1, fmaf(q3.z, w2, fmaf(q3.w, w3, a3))));
        }
        size_t o = ((size_t)blockIdx.x * K0_BLK + p0) * 256 + c;
        g_Qh[o] = a0; g_Qh[o + 256] = a1; g_Qh[o + 512] = a2; g_Qh[o + 768] = a3;
    }
}

// ============================== Main kernel ==================================
__global__ __launch_bounds__(THREADS, 1)
void attn_main_kernel(const float* __restrict__ inp,
                      const float* __restrict__ Wk, const float* __restrict__ bk,
                      const float* __restrict__ Wv, const float* __restrict__ bv,
                      float* __restrict__ out)
{
    extern __shared__ float sm[];
    char* A16 = (char*)sm + (size_t)O_A16 * 4;
    const int t   = threadIdx.x;
    const int wid = t >> 5;
    const int ln  = t & 31;
    const int base0 = blockIdx.x * PPB;
    const uint32_t a16_u32 = smem_u32(A16);

    // staging indices: thread t -> row k (0..31), float-col c4 (0,4,..,60)
    const int sk  = t >> 4;
    const int sc4 = (t & 15) * 4;

    // ---- prologue: stage tile 0 + QH0, weights, biases ----
    {
        int p0 = base0 < PTS ? base0 : PTS - 1;
        float4 xv = __ldg((const float4*)(inp + (size_t)p0 * 2048 + sk * 64 + sc4));
        float4 q4;
        if (t < 64) q4 = __ldg((const float4*)(g_Qh + (size_t)p0 * 256 + t * 4));

        // stage Wk^T / Wv^T as [256 n][68 f] fp32 (used only for fragment hoist)
        for (int i = t; i < 4096; i += THREADS) {       // i over [64 f][64 n4]
            int f = i >> 6, n0 = (i & 63) * 4;
            float4 a = __ldg((const float4*)Wk + i);
            sm[O_WKT + (n0 + 0) * 68 + f] = a.x;
            sm[O_WKT + (n0 + 1) * 68 + f] = a.y;
            sm[O_WKT + (n0 + 2) * 68 + f] = a.z;
            sm[O_WKT + (n0 + 3) * 68 + f] = a.w;
            float4 b = __ldg((const float4*)Wv + i);
            sm[O_WVT + (n0 + 0) * 68 + f] = b.x;
            sm[O_WVT + (n0 + 1) * 68 + f] = b.y;
            sm[O_WVT + (n0 + 2) * 68 + f] = b.z;
            sm[O_WVT + (n0 + 3) * 68 + f] = b.w;
        }
        if (t < 256) { sm[O_B + t] = bk[t]; sm[O_B + 256 + t] = bv[t]; }

        // fp16 tile 0
        *(uint2*)(A16 + sk * 144 + sc4 * 2) =
            make_uint2(pack_h2(xv.x, xv.y), pack_h2(xv.z, xv.w));
        if (t < 64)
            *(float4*)(sm + O_QH + t * 4) = q4;
        __syncthreads();
    }

    // ---- hoist fp16 B-fragments: warp wid -> proj (wid>>3), n-range (wid&7)*32 ----
    const int proj = wid >> 3;
    const int nb_  = (wid & 7) * 32;
    const int r0 = ln >> 2;           // fragment row group
    const int cc = (ln & 3) * 2;      // fragment k/col pair base
    const float* WT = sm + (proj ? O_WVT : O_WKT);
    float* OUT = sm + (proj ? O_VP : O_KP);
    uint32_t bfr[4][4][2];            // [j(n8)][s(k16)][2]
    float2   b2[4];
    #pragma unroll
    for (int j = 0; j < 4; ++j) {
        const int n = nb_ + j * 8 + r0;
        #pragma unroll
        for (int s = 0; s < 4; ++s) {
            const int kb = s * 16 + cc;
            bfr[j][s][0] = pack_h2(WT[n * 68 + kb],     WT[n * 68 + kb + 1]);
            bfr[j][s][1] = pack_h2(WT[n * 68 + kb + 8], WT[n * 68 + kb + 9]);
        }
        const int col = nb_ + j * 8 + cc;
        b2[j] = make_float2(sm[O_B + proj * 256 + col],
                            sm[O_B + proj * 256 + col + 1]);
    }
    // (WT smem never reused; no barrier needed after register hoist)

    // ldmatrix per-lane base: row = (ln&15), koff-half = (ln>>4)*8
    const uint32_t lm_base = a16_u32 + (uint32_t)(ln & 15) * 144 + (uint32_t)((ln >> 4) * 8) * 2;

    for (int r = 0; r < PPB; ++r) {
        int pt  = base0 + r;     if (pt  >= PTS) pt  = PTS - 1;
        int ptn = base0 + r + 1; if (ptn >= PTS) ptn = PTS - 1;
        const int buf = r & 1;

        // issue next point's loads early (consumed mid-round)
        float4 xv = __ldg((const float4*)(inp + (size_t)ptn * 2048 + sk * 64 + sc4));
        float4 q4;
        if (t < 64) q4 = __ldg((const float4*)(g_Qh + (size_t)ptn * 256 + t * 4));

        __syncthreads();     // B1: prev round's readers of KP/VP done

        // ---- P1: KP/VP via ldmatrix + mma m16n8k16 fp16 ----
        {
            float c[2][4][4];
            #pragma unroll
            for (int mi = 0; mi < 2; ++mi)
                #pragma unroll
                for (int j = 0; j < 4; ++j)
                    #pragma unroll
                    for (int q = 0; q < 4; ++q) c[mi][j][q] = 0.f;

            const uint32_t ab = lm_base + (uint32_t)buf * A_TILE_BYTES;
            #pragma unroll
            for (int s = 0; s < 4; ++s) {
                uint32_t a0[4], a1[4];
                ldmx4(a0, ab + s * 32);            // rows 0-15
                ldmx4(a1, ab + 2304 + s * 32);     // rows 16-31
                #pragma unroll
                for (int j = 0; j < 4; ++j) {
                    mma_f16(c[0][j], a0, bfr[j][s]);
                    mma_f16(c[1][j], a1, bfr[j][s]);
                }
            }
            // store with bias (fp32 exact)
            #pragma unroll
            for (int mi = 0; mi < 2; ++mi) {
                const int row = mi * 16 + r0;
                #pragma unroll
                for (int j = 0; j < 4; ++j) {
                    const int col = nb_ + j * 8 + cc;
                    const float2 bb = b2[j];
                    *(float2*)(OUT + row * 260 + col) =
                        make_float2(c[mi][j][0] + bb.x, c[mi][j][1] + bb.y);
                    *(float2*)(OUT + (row + 8) * 260 + col) =
                        make_float2(c[mi][j][2] + bb.x, c[mi][j][3] + bb.y);
                }
            }
        }

        // stage next tile (fp16) + next QH while P1 stores drain
        *(uint2*)(A16 + (buf ^ 1) * A_TILE_BYTES + sk * 144 + sc4 * 2) =
            make_uint2(pack_h2(xv.x, xv.y), pack_h2(xv.z, xv.w));
        if (t < 64)
            *(float4*)(sm + O_QH + (buf ^ 1) * 256 + t * 4) = q4;

        __syncthreads();     // B2: KP/VP visible

        // ---- P2+P3 merged: warp = head h. scores -> softmax -> output ----
        {
            const int h = wid;
            const int nb = 2 * h + (ln >> 4), kk = ln & 15;
            const float* kpP = sm + O_KP + nb * 260 + kk * 16;
            const float* qP  = sm + O_QH + buf * 256 + h * 16;
            float s = 0.f;
            #pragma unroll
            for (int d4 = 0; d4 < 4; ++d4)
                s = dot4(*(const float4*)(qP + d4 * 4),
                         *(const float4*)(kpP + d4 * 4), s);
            s *= 0.25f;                     // 1/sqrt(D)
            float m = s;
            #pragma unroll
            for (int off = 16; off; off >>= 1)
                m = fmaxf(m, __shfl_xor_sync(FULLMASK, m, off));
            float e = __expf(s - m);
            float ssum = e;
            #pragma unroll
            for (int off = 16; off; off >>= 1)
                ssum += __shfl_xor_sync(FULLMASK, ssum, off);
            const float w = e * __frcp_rn(ssum);   // lane k holds w[h,k]

            const int half = ln >> 4, d = ln & 15;
            const float* vrow = sm + O_VP + (2 * h + half) * 260 + d;
            float acc = 0.f;
            #pragma unroll
            for (int j = 0; j < 16; ++j) {
                const float wj = __shfl_sync(FULLMASK, w, half * 16 + j);
                acc = fmaf(wj, vrow[j * 16], acc);
            }
            acc += __shfl_xor_sync(FULLMASK, acc, 16);
            if (half == 0)
                out[(size_t)pt * 256 + h * 16 + d] = acc;
        }
        // next round's B1 gates KP/VP/A reuse
    }
}

// ================================ launch =====================================
extern "C" void kernel_launch(void* const* d_in, const int* in_sizes, int n_in,
                              void* d_out, int out_size) {
    const float* inp   = (const float*)d_in[0];
    const float* query = (const float*)d_in[1];
    const float* Wq    = (const float*)d_in[2];
    const float* bq    = (const float*)d_in[3];
    const float* Wk    = (const float*)d_in[4];
    const float* bk    = (const float*)d_in[5];
    const float* Wv    = (const float*)d_in[6];
    const float* bv    = (const float*)d_in[7];
    float* out = (float*)d_out;

    cudaFuncSetAttribute(qproj_kernel,
                         cudaFuncAttributeMaxDynamicSharedMemorySize, K0_SMEM);
    cudaFuncSetAttribute(attn_main_kernel,
                         cudaFuncAttributeMaxDynamicSharedMemorySize, SMEM_BYTES);

    qproj_kernel<<<PTS / K0_BLK, 256, K0_SMEM>>>(query, Wq, bq);
    attn_main_kernel<<<GRID, THREADS, SMEM_BYTES>>>(inp, Wk, bk, Wv, bv, out);
}

// round 12
// speedup vs baseline: 3.7387x; 1.3511x over previous
#include <cuda_runtime.h>
#include <cuda_fp16.h>
#include <cstdint>
#include <cstddef>

// ---------------------------------------------------------------------------
// AttentionLayer B=4,N=4096,Kn=32,F=64,H=16,D=16 (fp32 in/out)
//   KP = inp@Wk + bk [32x256], VP = inp@Wv + bv
//   K[h,k,d] = KP[2h+(k>>4), (k&15)*16+d]  (same for V)
//   s = 0.25*Qh_h.K ; w = softmax_k ; out = sum_k w*V
// P1 via ldmatrix + mma.sync.m16n8k16 fp16. KP/VP stored fp16 with a
// bijective quad-swizzle (q ^= q>>3) -> conflict-free stores and reads.
// Qh = query@Wq + bq in fp32 (kernel 0).
// ---------------------------------------------------------------------------

#define FULLMASK 0xffffffffu

constexpr int PTS     = 16384;
constexpr int GRID    = 152;
constexpr int PPB     = 108;
constexpr int THREADS = 512;

__device__ float g_Qh[(size_t)PTS * 256];

// smem offsets (floats)
constexpr int O_WKT = 0;                    // Wk^T [256 n][68 f] fp32 (init only)
constexpr int O_WVT = 17408;
constexpr int O_KP  = 34816;                // fp16 [32][264] halfs = 4224 floats
constexpr int O_VP  = 39040;                // fp16 [32][280] halfs = 4480 floats
constexpr int O_A16 = 43520;                // fp16 tile: 2 x [32][72] halfs = 2304 floats
constexpr int O_QH  = 45824;                // 2 x 256 fp32
constexpr int O_B   = 46336;                // bk(256) | bv(256) fp32
constexpr int SMEM_FLOATS = 46848;          // 187392 B
constexpr int SMEM_BYTES  = SMEM_FLOATS * 4;

constexpr int A_TILE_BYTES = 32 * 144;      // fp16 A buffer (row stride 144 B)
constexpr int KP_STRIDE = 264;              // halfs per KP row (132 words == 4 mod 32)
constexpr int VP_STRIDE = 280;              // halfs per VP row (140 words == 12 mod 32)

// half-offset of chunk kk's halfs 0-7: quad perm(2kk), perm(q)=q^(q>>3).
// halfs 8-15 live at (CHSW ^ 8). Bijective: all 32 quads covered exactly once.
__device__ __forceinline__ int CHSW(int kk) {
    return (((2 * kk) ^ (kk >> 2)) << 3);
}

__device__ __forceinline__ uint32_t pack_h2(float lo, float hi) {
    __half2 h = __floats2half2_rn(lo, hi);
    return *(uint32_t*)&h;
}
__device__ __forceinline__ void mma_f16(float c[4], const uint32_t a[4], const uint32_t b[2]) {
    asm volatile(
        "mma.sync.aligned.m16n8k16.row.col.f32.f16.f16.f32 "
        "{%0,%1,%2,%3}, {%4,%5,%6,%7}, {%8,%9}, {%0,%1,%2,%3};"
        : "+f"(c[0]), "+f"(c[1]), "+f"(c[2]), "+f"(c[3])
        : "r"(a[0]), "r"(a[1]), "r"(a[2]), "r"(a[3]), "r"(b[0]), "r"(b[1]));
}
__device__ __forceinline__ void ldmx4(uint32_t a[4], uint32_t addr) {
    asm volatile("ldmatrix.sync.aligned.m8n8.x4.shared.b16 {%0,%1,%2,%3}, [%4];"
                 : "=r"(a[0]), "=r"(a[1]), "=r"(a[2]), "=r"(a[3]) : "r"(addr));
}
__device__ __forceinline__ uint32_t smem_u32(const void* p) {
    uint32_t a;
    asm("{ .reg .u64 t; cvta.to.shared.u64 t, %1; cvt.u32.u64 %0, t; }" : "=r"(a) : "l"(p));
    return a;
}
__device__ __forceinline__ float2 h2f(uint32_t u) {
    return __half22float2(*(__half2*)&u);
}

// ===================== Kernel 0: Qh = query @ Wq + bq (fp32) ================
constexpr int K0_BLK  = 64;
constexpr int K0_SMEM = (64 * 256 + K0_BLK * 64) * 4;   // 80 KB -> 2 CTA/SM

__global__ __launch_bounds__(256, 2)
void qproj_kernel(const float* __restrict__ query, const float* __restrict__ Wq,
                  const float* __restrict__ bq)
{
    extern __shared__ float sm[];
    float* wq = sm;
    float* q  = sm + 64 * 256;
    const int t = threadIdx.x;

    for (int i = t; i < 4096; i += 256)
        ((float4*)wq)[i] = __ldg((const float4*)Wq + i);
    const float4* qsrc = (const float4*)(query + (size_t)blockIdx.x * K0_BLK * 64);
    for (int i = t; i < K0_BLK * 16; i += 256)
        ((float4*)q)[i] = __ldg(qsrc + i);
    __syncthreads();

    const int c = t;
    const float bqc = bq[c];
    for (int p0 = 0; p0 < K0_BLK; p0 += 4) {
        float a0 = bqc, a1 = bqc, a2 = bqc, a3 = bqc;
        #pragma unroll
        for (int f4 = 0; f4 < 16; ++f4) {
            float4 q0 = *(const float4*)(q + (p0 + 0) * 64 + f4 * 4);
            float4 q1 = *(const float4*)(q + (p0 + 1) * 64 + f4 * 4);
            float4 q2 = *(const float4*)(q + (p0 + 2) * 64 + f4 * 4);
            float4 q3 = *(const float4*)(q + (p0 + 3) * 64 + f4 * 4);
            float w0 = wq[(f4 * 4 + 0) * 256 + c];
            float w1 = wq[(f4 * 4 + 1) * 256 + c];
            float w2 = wq[(f4 * 4 + 2) * 256 + c];
            float w3 = wq[(f4 * 4 + 3) * 256 + c];
            a0 = fmaf(q0.x, w0, fmaf(q0.y, w1, fmaf(q0.z, w2, fmaf(q0.w, w3, a0))));
            a1 = fmaf(q1.x, w0, fmaf(q1.y, w1, fmaf(q1.z, w2, fmaf(q1.w, w3, a1))));
            a2 = fmaf(q2.x, w0, fmaf(q2.y, w1, fmaf(q2.z, w2, fmaf(q2.w, w3, a2))));
            a3 = fmaf(q3.x, w0, fmaf(q3.y, w1, fmaf(q3.z, w2, fmaf(q3.w, w3, a3))));
        }
        size_t o = ((size_t)blockIdx.x * K0_BLK + p0) * 256 + c;
        g_Qh[o] = a0; g_Qh[o + 256] = a1; g_Qh[o + 512] = a2; g_Qh[o + 768] = a3;
    }
}

// ============================== Main kernel ==================================
__global__ __launch_bounds__(THREADS, 1)
void attn_main_kernel(const float* __restrict__ inp,
                      const float* __restrict__ Wk, const float* __restrict__ bk,
                      const float* __restrict__ Wv, const float* __restrict__ bv,
                      float* __restrict__ out)
{
    extern __shared__ float sm[];
    char* A16 = (char*)sm + (size_t)O_A16 * 4;
    __half* KPH = (__half*)(sm + O_KP);
    __half* VPH = (__half*)(sm + O_VP);
    const int t   = threadIdx.x;
    const int wid = t >> 5;
    const int ln  = t & 31;
    const int base0 = blockIdx.x * PPB;
    const uint32_t a16_u32 = smem_u32(A16);

    // staging indices: thread t -> row k (0..31), float-col c4 (0,4,..,60)
    const int sk  = t >> 4;
    const int sc4 = (t & 15) * 4;

    // ---- prologue: stage tile 0 + QH0, weights, biases ----
    {
        int p0 = base0 < PTS ? base0 : PTS - 1;
        float4 xv = __ldg((const float4*)(inp + (size_t)p0 * 2048 + sk * 64 + sc4));
        float4 q4;
        if (t < 64) q4 = __ldg((const float4*)(g_Qh + (size_t)p0 * 256 + t * 4));

        for (int i = t; i < 4096; i += THREADS) {       // i over [64 f][64 n4]
            int f = i >> 6, n0 = (i & 63) * 4;
            float4 a = __ldg((const float4*)Wk + i);
            sm[O_WKT + (n0 + 0) * 68 + f] = a.x;
            sm[O_WKT + (n0 + 1) * 68 + f] = a.y;
            sm[O_WKT + (n0 + 2) * 68 + f] = a.z;
            sm[O_WKT + (n0 + 3) * 68 + f] = a.w;
            float4 b = __ldg((const float4*)Wv + i);
            sm[O_WVT + (n0 + 0) * 68 + f] = b.x;
            sm[O_WVT + (n0 + 1) * 68 + f] = b.y;
            sm[O_WVT + (n0 + 2) * 68 + f] = b.z;
            sm[O_WVT + (n0 + 3) * 68 + f] = b.w;
        }
        if (t < 256) { sm[O_B + t] = bk[t]; sm[O_B + 256 + t] = bv[t]; }

        *(uint2*)(A16 + sk * 144 + sc4 * 2) =
            make_uint2(pack_h2(xv.x, xv.y), pack_h2(xv.z, xv.w));
        if (t < 64)
            *(float4*)(sm + O_QH + t * 4) = q4;
        __syncthreads();
    }

    // ---- hoist fp16 B-fragments: warp wid -> proj (wid>>3), n-range (wid&7)*32 ----
    const int proj = wid >> 3;
    const int nb_  = (wid & 7) * 32;
    const int r0 = ln >> 2;
    const int cc = (ln & 3) * 2;
    const float* WT = sm + (proj ? O_WVT : O_WKT);
    __half* OUTH = proj ? VPH : KPH;
    const int OSTRIDE = proj ? VP_STRIDE : KP_STRIDE;
    uint32_t bfr[4][4][2];            // [j(n8)][s(k16)][2]
    float2   b2[4];
    #pragma unroll
    for (int j = 0; j < 4; ++j) {
        const int n = nb_ + j * 8 + r0;
        #pragma unroll
        for (int s = 0; s < 4; ++s) {
            const int kb = s * 16 + cc;
            bfr[j][s][0] = pack_h2(WT[n * 68 + kb],     WT[n * 68 + kb + 1]);
            bfr[j][s][1] = pack_h2(WT[n * 68 + kb + 8], WT[n * 68 + kb + 9]);
        }
        const int col = nb_ + j * 8 + cc;
        b2[j] = make_float2(sm[O_B + proj * 256 + col],
                            sm[O_B + proj * 256 + col + 1]);
    }

    // ldmatrix per-lane base
    const uint32_t lm_base = a16_u32 + (uint32_t)(ln & 15) * 144 + (uint32_t)((ln >> 4) * 8) * 2;

    for (int r = 0; r < PPB; ++r) {
        int pt  = base0 + r;     if (pt  >= PTS) pt  = PTS - 1;
        int ptn = base0 + r + 1; if (ptn >= PTS) ptn = PTS - 1;
        const int buf = r & 1;

        // issue next point's loads early (consumed mid-round)
        float4 xv = __ldg((const float4*)(inp + (size_t)ptn * 2048 + sk * 64 + sc4));
        float4 q4;
        if (t < 64) q4 = __ldg((const float4*)(g_Qh + (size_t)ptn * 256 + t * 4));

        __syncthreads();     // B1: prev round's readers of KP/VP done

        // ---- P1: KP/VP via ldmatrix + mma m16n8k16 fp16, store fp16 swizzled ----
        {
            float c[2][4][4];
            #pragma unroll
            for (int mi = 0; mi < 2; ++mi)
                #pragma unroll
                for (int j = 0; j < 4; ++j)
                    #pragma unroll
                    for (int q = 0; q < 4; ++q) c[mi][j][q] = 0.f;

            const uint32_t ab = lm_base + (uint32_t)buf * A_TILE_BYTES;
            #pragma unroll
            for (int s = 0; s < 4; ++s) {
                uint32_t a0[4], a1[4];
                ldmx4(a0, ab + s * 32);            // rows 0-15
                ldmx4(a1, ab + 2304 + s * 32);     // rows 16-31
                #pragma unroll
                for (int j = 0; j < 4; ++j) {
                    mma_f16(c[0][j], a0, bfr[j][s]);
                    mma_f16(c[1][j], a1, bfr[j][s]);
                }
            }
            // store fp16 with bias; chunk = nb_/16 + (j>>1); quad sel = j&1
            #pragma unroll
            for (int mi = 0; mi < 2; ++mi) {
                const int row = mi * 16 + r0;
                #pragma unroll
                for (int j = 0; j < 4; ++j) {
                    const int off = (CHSW((nb_ >> 4) + (j >> 1)) ^ ((j & 1) << 3)) + cc;
                    const float2 bb = b2[j];
                    *(__half2*)(OUTH + row * OSTRIDE + off) =
                        __floats2half2_rn(c[mi][j][0] + bb.x, c[mi][j][1] + bb.y);
                    *(__half2*)(OUTH + (row + 8) * OSTRIDE + off) =
                        __floats2half2_rn(c[mi][j][2] + bb.x, c[mi][j][3] + bb.y);
                }
            }
        }

        // stage next tile (fp16) + next QH while P1 stores drain
        *(uint2*)(A16 + (buf ^ 1) * A_TILE_BYTES + sk * 144 + sc4 * 2) =
            make_uint2(pack_h2(xv.x, xv.y), pack_h2(xv.z, xv.w));
        if (t < 64)
            *(float4*)(sm + O_QH + (buf ^ 1) * 256 + t * 4) = q4;

        __syncthreads();     // B2: KP/VP visible

        // ---- P2: scores + softmax (warp = head h, lane = k) ----
        float w;
        const int h = wid;
        {
            const int nb = 2 * h + (ln >> 4), kk = ln & 15;
            const __half* rowp = KPH + nb * KP_STRIDE;
            const int ho = CHSW(kk);
            uint4 u0 = *(const uint4*)(rowp + ho);        // halfs 0-7
            uint4 u1 = *(const uint4*)(rowp + (ho ^ 8));  // halfs 8-15
            const float* qP = sm + O_QH + buf * 256 + h * 16;
            float4 qa = *(const float4*)(qP);
            float4 qb = *(const float4*)(qP + 4);
            float4 qc = *(const float4*)(qP + 8);
            float4 qd = *(const float4*)(qP + 12);
            float2 f0 = h2f(u0.x), f1 = h2f(u0.y), f2 = h2f(u0.z), f3 = h2f(u0.w);
            float2 f4 = h2f(u1.x), f5 = h2f(u1.y), f6 = h2f(u1.z), f7 = h2f(u1.w);
            float s = 0.f;
            s = fmaf(qa.x, f0.x, fmaf(qa.y, f0.y, fmaf(qa.z, f1.x, fmaf(qa.w, f1.y, s))));
            s = fmaf(qb.x, f2.x, fmaf(qb.y, f2.y, fmaf(qb.z, f3.x, fmaf(qb.w, f3.y, s))));
            s = fmaf(qc.x, f4.x, fmaf(qc.y, f4.y, fmaf(qc.z, f5.x, fmaf(qc.w, f5.y, s))));
            s = fmaf(qd.x, f6.x, fmaf(qd.y, f6.y, fmaf(qd.z, f7.x, fmaf(qd.w, f7.y, s))));
            s *= 0.25f;                     // 1/sqrt(D)
            float m = s;
            #pragma unroll
            for (int off = 16; off; off >>= 1)
                m = fmaxf(m, __shfl_xor_sync(FULLMASK, m, off));
            float e = __expf(s - m);
            float ssum = e;
            #pragma unroll
            for (int off = 16; off; off >>= 1)
                ssum += __shfl_xor_sync(FULLMASK, ssum, off);
            w = e * __frcp_rn(ssum);        // lane k holds w[h,k]
        }

        // ---- P3: output. lane = (half, d): scalar-half reads, conflict-free ----
        {
            const int half = ln >> 4, d = ln & 15;
            const __half* vr = VPH + (2 * h + half) * VP_STRIDE;
            const int dsel = (d >> 3) << 3, dw = d & 7;
            float acc = 0.f;
            #pragma unroll
            for (int j = 0; j < 16; ++j) {
                const float wj = __shfl_sync(FULLMASK, w, half * 16 + j);
                acc = fmaf(wj, __half2float(vr[(CHSW(j) ^ dsel) + dw]), acc);
            }
            acc += __shfl_xor_sync(FULLMASK, acc, 16);
            if (half == 0)
                out[(size_t)pt * 256 + h * 16 + d] = acc;
        }
        // next round's B1 gates KP/VP/A reuse
    }
}

// ================================ launch =====================================
extern "C" void kernel_launch(void* const* d_in, const int* in_sizes, int n_in,
                              void* d_out, int out_size) {
    const float* inp   = (const float*)d_in[0];
    const float* query = (const float*)d_in[1];
    const float* Wq    = (const float*)d_in[2];
    const float* bq    = (const float*)d_in[3];
    const float* Wk    = (const float*)d_in[4];
    const float* bk    = (const float*)d_in[5];
    const float* Wv    = (const float*)d_in[6];
    const float* bv    = (const float*)d_in[7];
    float* out = (float*)d_out;

    cudaFuncSetAttribute(qproj_kernel,
                         cudaFuncAttributeMaxDynamicSharedMemorySize, K0_SMEM);
    cudaFuncSetAttribute(attn_main_kernel,
                         cudaFuncAttributeMaxDynamicSharedMemorySize, SMEM_BYTES);

    qproj_kernel<<<PTS / K0_BLK, 256, K0_SMEM>>>(query, Wq, bq);
    attn_main_kernel<<<GRID, THREADS, SMEM_BYTES>>>(inp, Wk, bk, Wv, bv, out);
}